// round 4
// baseline (speedup 1.0000x reference)
#include <cuda_runtime.h>
#include <cuda_bf16.h>
#include <math.h>
#include <stdint.h>

// ---------------------------------------------------------------------------
// Problem constants
// ---------------------------------------------------------------------------
#define BB   32
#define SS   128
#define HH   1024
#define G4   4096
#define VV   32000
#define MBS  4096                      // B*S
#define LOGITS 131072000LL             // B*S*V

// ---------------------------------------------------------------------------
// Device scratch (static __device__ arrays: the sanctioned scratch mechanism)
// ---------------------------------------------------------------------------
__device__ float    g_emb [MBS * HH];              // 16 MB  [m][H]
__device__ float    g_xp  [2L * MBS * G4];         // 128 MB [dir][m][4H]
__device__ float    g_comb[MBS * 2 * HH];          // 32 MB  [m][2H]
__device__ float    g_whh [2L * HH * G4];          // 32 MB  tf32-rounded W_hh
__device__ float    g_h   [2 * 2 * BB * HH];       // [dir][pingpong][b][H]
__device__ unsigned g_bar [SS];                    // barrier counters (BSS zero)

// ---------------------------------------------------------------------------
// Helpers
// ---------------------------------------------------------------------------
__device__ __forceinline__ float tf32r(float x) {
    float y;
    asm("cvt.rna.tf32.f32 %0, %1;" : "=f"(y) : "f"(x));
    return y;
}
__device__ __forceinline__ float ldcg(const float* p) {
    float v;
    asm volatile("ld.global.cg.f32 %0, [%1];" : "=f"(v) : "l"(p));
    return v;
}
__device__ __forceinline__ float4 ldcg4(const float4* p) {
    float4 v;
    asm volatile("ld.global.cg.v4.f32 {%0,%1,%2,%3}, [%4];"
                 : "=f"(v.x), "=f"(v.y), "=f"(v.z), "=f"(v.w) : "l"(p));
    return v;
}
__device__ __forceinline__ void mma_tf32(float* d, const unsigned* a, const unsigned* b) {
    asm volatile(
        "mma.sync.aligned.m16n8k8.row.col.f32.tf32.tf32.f32 "
        "{%0,%1,%2,%3},{%4,%5,%6,%7},{%8,%9},{%0,%1,%2,%3};"
        : "+f"(d[0]), "+f"(d[1]), "+f"(d[2]), "+f"(d[3])
        : "r"(a[0]), "r"(a[1]), "r"(a[2]), "r"(a[3]), "r"(b[0]), "r"(b[1]));
}
__device__ __forceinline__ float sigm(float x) { return 1.f / (1.f + expf(-x)); }

// ---------------------------------------------------------------------------
// Kernel: embedding gather (one row per CTA; 256 thr * float4 = 1024 floats)
// ---------------------------------------------------------------------------
__global__ void embed_kernel(const int* __restrict__ x,
                             const float* __restrict__ embed) {
    int m = blockIdx.x;
    int idx = x[m];
    const float4* src = (const float4*)(embed + (size_t)idx * HH);
    float4* dst = (float4*)(g_emb + (size_t)m * HH);
    dst[threadIdx.x] = src[threadIdx.x];
}

// ---------------------------------------------------------------------------
// Kernel: pre-round W_hh (both dirs) to tf32 so the recurrence loop is clean
// ---------------------------------------------------------------------------
__global__ void round_whh(const float* __restrict__ wf, const float* __restrict__ wb) {
    size_t n = (size_t)HH * G4;
    for (size_t i = (size_t)blockIdx.x * blockDim.x + threadIdx.x; i < n;
         i += (size_t)gridDim.x * blockDim.x) {
        g_whh[i]     = tf32r(wf[i]);
        g_whh[n + i] = tf32r(wb[i]);
    }
}

// ---------------------------------------------------------------------------
// Kernel: tf32 GEMM  C[M,N] = A[M,K] @ B[K,N] + bias[N]
// 128x128 CTA tile, K-step 16, 256 threads (8 warps as 4x2, warp tile 32x64),
// register prefetch double-buffer, rna-tf32 rounding at SMEM store.
// Requires M%128==0, N%128==0, K%16==0 (true for all three uses).
// ---------------------------------------------------------------------------
__global__ __launch_bounds__(256) void gemm_tf32(
    const float* __restrict__ A, const float* __restrict__ B,
    const float* __restrict__ bias, float* __restrict__ C,
    int M, int N, int K)
{
    __shared__ __align__(16) float As[128 * 20];   // [row][k], pitch 20
    __shared__ __align__(16) float Bs[16 * 136];   // [k][col], pitch 136

    int tiles_m = M >> 7;
    int mt = blockIdx.x % tiles_m;
    int nt = blockIdx.x / tiles_m;
    size_t m0 = (size_t)mt * 128;
    size_t n0 = (size_t)nt * 128;

    int tid = threadIdx.x;
    int lane = tid & 31, warp = tid >> 5;
    int gid = lane >> 2, tq = lane & 3;
    int wm = warp >> 1, wn = warp & 1;

    float acc[2][8][4];
#pragma unroll
    for (int i = 0; i < 2; i++)
#pragma unroll
        for (int j = 0; j < 8; j++)
#pragma unroll
            for (int e = 0; e < 4; e++) acc[i][j][e] = 0.f;

    // per-thread tile-load assignment: 2 float4 from A, 2 from B
    int ca0 = tid * 2, ca1 = ca0 + 1;
    int ar0 = ca0 >> 2, as0 = (ca0 & 3) << 2;
    int ar1 = ca1 >> 2, as1 = (ca1 & 3) << 2;
    int br0 = ca0 >> 5, bs0 = (ca0 & 31) << 2;
    int br1 = ca1 >> 5, bs1 = (ca1 & 31) << 2;

    const float* Ab = A + m0 * (size_t)K;
    const float* Bb = B + n0;

    float4 pa0, pa1, pb0, pb1;
    int KT = K >> 4;

    // prefetch tile 0
    {
        size_t k0 = 0;
        pa0 = *(const float4*)(Ab + (size_t)ar0 * K + k0 + as0);
        pa1 = *(const float4*)(Ab + (size_t)ar1 * K + k0 + as1);
        pb0 = *(const float4*)(Bb + (k0 + br0) * (size_t)N + bs0);
        pb1 = *(const float4*)(Bb + (k0 + br1) * (size_t)N + bs1);
    }

    for (int kt = 0; kt < KT; kt++) {
        // store current tile to SMEM with rna-tf32 rounding
        {
            float4 q;
            q.x = tf32r(pa0.x); q.y = tf32r(pa0.y); q.z = tf32r(pa0.z); q.w = tf32r(pa0.w);
            *(float4*)(As + ar0 * 20 + as0) = q;
            q.x = tf32r(pa1.x); q.y = tf32r(pa1.y); q.z = tf32r(pa1.z); q.w = tf32r(pa1.w);
            *(float4*)(As + ar1 * 20 + as1) = q;
            q.x = tf32r(pb0.x); q.y = tf32r(pb0.y); q.z = tf32r(pb0.z); q.w = tf32r(pb0.w);
            *(float4*)(Bs + br0 * 136 + bs0) = q;
            q.x = tf32r(pb1.x); q.y = tf32r(pb1.y); q.z = tf32r(pb1.z); q.w = tf32r(pb1.w);
            *(float4*)(Bs + br1 * 136 + bs1) = q;
        }
        __syncthreads();
        if (kt + 1 < KT) {
            size_t k0 = (size_t)(kt + 1) << 4;
            pa0 = *(const float4*)(Ab + (size_t)ar0 * K + k0 + as0);
            pa1 = *(const float4*)(Ab + (size_t)ar1 * K + k0 + as1);
            pb0 = *(const float4*)(Bb + (k0 + br0) * (size_t)N + bs0);
            pb1 = *(const float4*)(Bb + (k0 + br1) * (size_t)N + bs1);
        }
#pragma unroll
        for (int ks = 0; ks < 16; ks += 8) {
            unsigned a[2][4], b[8][2];
#pragma unroll
            for (int mi = 0; mi < 2; mi++) {
                int r = wm * 32 + mi * 16 + gid;
                a[mi][0] = __float_as_uint(As[r * 20 + ks + tq]);
                a[mi][1] = __float_as_uint(As[(r + 8) * 20 + ks + tq]);
                a[mi][2] = __float_as_uint(As[r * 20 + ks + tq + 4]);
                a[mi][3] = __float_as_uint(As[(r + 8) * 20 + ks + tq + 4]);
            }
#pragma unroll
            for (int ni = 0; ni < 8; ni++) {
                int c = wn * 64 + ni * 8 + gid;
                b[ni][0] = __float_as_uint(Bs[(ks + tq) * 136 + c]);
                b[ni][1] = __float_as_uint(Bs[(ks + tq + 4) * 136 + c]);
            }
#pragma unroll
            for (int mi = 0; mi < 2; mi++)
#pragma unroll
                for (int ni = 0; ni < 8; ni++)
                    mma_tf32(acc[mi][ni], a[mi], b[ni]);
        }
        __syncthreads();
    }

    // epilogue: add bias, store fp32
#pragma unroll
    for (int mi = 0; mi < 2; mi++) {
#pragma unroll
        for (int ni = 0; ni < 8; ni++) {
            size_t r = m0 + wm * 32 + mi * 16 + gid;
            size_t c = n0 + wn * 64 + ni * 8 + 2 * tq;
            float2 bv = *(const float2*)(bias + c);
            float2 o0 = make_float2(acc[mi][ni][0] + bv.x, acc[mi][ni][1] + bv.y);
            float2 o1 = make_float2(acc[mi][ni][2] + bv.x, acc[mi][ni][3] + bv.y);
            *(float2*)(C + r * (size_t)N + c) = o0;
            *(float2*)(C + (r + 8) * (size_t)N + c) = o1;
        }
    }
}

// ---------------------------------------------------------------------------
// Grid barrier: per-step counters, self-resetting for graph replay
// ---------------------------------------------------------------------------
__device__ __forceinline__ void gbar(int idx) {
    __threadfence();
    __syncthreads();
    if (threadIdx.x == 0) {
        unsigned a = atomicAdd(&g_bar[idx], 1u);
        if (a + 1u < 128u) {
            while (((volatile unsigned*)g_bar)[idx] < 128u) __nanosleep(64);
        }
        if (blockIdx.x == 0 && idx > 0) ((volatile unsigned*)g_bar)[idx - 1] = 0u;
    }
    __syncthreads();
}

// ---------------------------------------------------------------------------
// Kernel: persistent bidirectional LSTM recurrence.
// 128 CTAs x 256 thr. CTAs [0,64) forward, [64,128) backward. CTA owns 16
// hidden units -> 64 gate columns (16 per gate). 8 warps: warp w computes
// gate (w&3) over K-half (w>>2) via tf32 mma; halves summed in elementwise.
// h exchanged via global ping-pong (tf32-rounded), read with ld.global.cg.
// ---------------------------------------------------------------------------
__global__ __launch_bounds__(256, 1) void lstm_kernel(
    const float* __restrict__ bhh_f, const float* __restrict__ bhh_b,
    float* __restrict__ out, int has_states)
{
    extern __shared__ float sm[];
    float* h_s    = sm;                     // [32][1028]
    float* g_s    = sm + 32 * 1028;         // [64][68]  (khalf*32+b rows)
    float* c_s    = g_s + 64 * 68;          // [512]
    float* bias_s = c_s + 512;              // [64]

    int dir = blockIdx.x >> 6;
    int cid = blockIdx.x & 63;
    int j0  = cid * 16;
    const float* Wd = g_whh + (size_t)dir * HH * G4;
    const float* bh = dir ? bhh_b : bhh_f;
    const float* xp = g_xp + (size_t)dir * MBS * G4;
    float* hbuf = g_h + (size_t)dir * 2 * BB * HH;

    int tid = threadIdx.x;
    int lane = tid & 31, warp = tid >> 5;
    int gid = lane >> 2, tq = lane & 3;
    int gate = warp & 3, kh = warp >> 2;

    for (int i = tid; i < 512; i += 256) c_s[i] = 0.f;
    if (tid < 64) bias_s[tid] = bh[(tid >> 4) * HH + j0 + (tid & 15)];
    for (int i = cid * 256 + tid; i < BB * HH; i += 64 * 256) hbuf[i] = 0.f;
    gbar(0);

    const float* Wc = Wd + gate * 1024 + j0;   // W[k][col]: + k*G4 + (ni*8+gid)

    for (int step = 0; step < SS; step++) {
        int tseq = dir ? (SS - 1 - step) : step;
        int cur = step & 1, nxt = cur ^ 1;
        const float* hg = hbuf + cur * BB * HH;

        // copy h -> SMEM (L1 bypass: producer is a different SM)
        for (int idx = tid; idx < 8192; idx += 256) {
            int r = idx >> 8, c4 = (idx & 255) << 2;
            float4 v = ldcg4((const float4*)(hg + r * HH + c4));
            *(float4*)(h_s + r * 1028 + c4) = v;
        }
        __syncthreads();

        // gates = h @ W_hh (my 64-column slice), tf32 mma
        float acc[2][2][4];
#pragma unroll
        for (int i = 0; i < 2; i++)
#pragma unroll
            for (int j = 0; j < 2; j++)
#pragma unroll
                for (int e = 0; e < 4; e++) acc[i][j][e] = 0.f;

        int kend = kh * 512 + 512;
#pragma unroll 4
        for (int kb = kh * 512; kb < kend; kb += 8) {
            unsigned a[2][4];
#pragma unroll
            for (int mi = 0; mi < 2; mi++) {
                int r = mi * 16 + gid;
                a[mi][0] = __float_as_uint(h_s[r * 1028 + kb + tq]);
                a[mi][1] = __float_as_uint(h_s[(r + 8) * 1028 + kb + tq]);
                a[mi][2] = __float_as_uint(h_s[r * 1028 + kb + tq + 4]);
                a[mi][3] = __float_as_uint(h_s[(r + 8) * 1028 + kb + tq + 4]);
            }
#pragma unroll
            for (int ni = 0; ni < 2; ni++) {
                unsigned bf[2];
                bf[0] = __float_as_uint(ldcg(Wc + (size_t)(kb + tq) * G4 + ni * 8 + gid));
                bf[1] = __float_as_uint(ldcg(Wc + (size_t)(kb + tq + 4) * G4 + ni * 8 + gid));
                mma_tf32(acc[0][ni], a[0], bf);
                mma_tf32(acc[1][ni], a[1], bf);
            }
        }

        // store gate partials to SMEM
        float* gp = g_s + (kh * 32) * 68 + gate * 16;
#pragma unroll
        for (int mi = 0; mi < 2; mi++)
#pragma unroll
            for (int ni = 0; ni < 2; ni++) {
                int r = mi * 16 + gid, c = ni * 8 + 2 * tq;
                gp[r * 68 + c]         = acc[mi][ni][0];
                gp[r * 68 + c + 1]     = acc[mi][ni][1];
                gp[(r + 8) * 68 + c]     = acc[mi][ni][2];
                gp[(r + 8) * 68 + c + 1] = acc[mi][ni][3];
            }
        __syncthreads();

        // elementwise LSTM update (512 (b,j) items)
        float* hn = hbuf + nxt * BB * HH;
        for (int it = tid; it < 512; it += 256) {
            int b = it >> 4, jj = it & 15;
            const float* xr = xp + ((size_t)(b * SS + tseq)) * G4 + j0 + jj;
            float gq[4];
#pragma unroll
            for (int q = 0; q < 4; q++)
                gq[q] = g_s[b * 68 + q * 16 + jj] + g_s[(32 + b) * 68 + q * 16 + jj]
                      + xr[(size_t)q * 1024] + bias_s[q * 16 + jj];
            float iv = sigm(gq[0]);
            float fv = sigm(gq[1]);
            float gv = tanhf(gq[2]);
            float ov = sigm(gq[3]);
            float c = fv * c_s[it] + iv * gv;
            float h = ov * tanhf(c);
            c_s[it] = c;
            hn[b * HH + j0 + jj] = tf32r(h);
            g_comb[((size_t)(b * SS + tseq)) * 2 * HH + dir * HH + j0 + jj] = h;
            if (has_states && step == SS - 1) {
                size_t base = LOGITS + (size_t)dir * 2 * BB * HH;
                out[base + b * HH + j0 + jj] = h;            // hT
                out[base + BB * HH + b * HH + j0 + jj] = c;  // cT
            }
        }
        if (step < SS - 1) gbar(step + 1);
        else __syncthreads();
    }
    if (blockIdx.x == 0 && threadIdx.x == 0)
        ((volatile unsigned*)g_bar)[SS - 1] = 0u;
}

// ---------------------------------------------------------------------------
// Launch
// ---------------------------------------------------------------------------
extern "C" void kernel_launch(void* const* d_in, const int* in_sizes, int n_in,
                              void* d_out, int out_size) {
    const int*   x      = (const int*)d_in[0];
    const float* embed  = (const float*)d_in[1];
    const float* W_ih_f = (const float*)d_in[2];
    const float* b_ih_f = (const float*)d_in[3];
    const float* W_hh_f = (const float*)d_in[4];
    const float* b_hh_f = (const float*)d_in[5];
    const float* W_ih_b = (const float*)d_in[6];
    const float* b_ih_b = (const float*)d_in[7];
    const float* W_hh_b = (const float*)d_in[8];
    const float* b_hh_b = (const float*)d_in[9];
    const float* W_out  = (const float*)d_in[10];
    const float* b_out  = (const float*)d_in[11];
    float* out = (float*)d_out;

    void *pe, *pxp, *pcomb;
    cudaGetSymbolAddress(&pe, g_emb);
    cudaGetSymbolAddress(&pxp, g_xp);
    cudaGetSymbolAddress(&pcomb, g_comb);
    float* emb  = (float*)pe;
    float* xp   = (float*)pxp;
    float* comb = (float*)pcomb;

    embed_kernel<<<MBS, 256>>>(x, embed);
    round_whh<<<512, 256>>>(W_hh_f, W_hh_b);

    // input projections: [4096,1024] @ [1024,4096]
    gemm_tf32<<<32 * 32, 256>>>(emb, W_ih_f, b_ih_f, xp, MBS, G4, HH);
    gemm_tf32<<<32 * 32, 256>>>(emb, W_ih_b, b_ih_b, xp + (size_t)MBS * G4, MBS, G4, HH);

    int smem = (32 * 1028 + 64 * 68 + 512 + 64) * 4;
    cudaFuncSetAttribute(lstm_kernel, cudaFuncAttributeMaxDynamicSharedMemorySize, smem);
    long long need = LOGITS + 4LL * BB * HH;
    int has_states = ((long long)out_size >= need) ? 1 : 0;
    lstm_kernel<<<128, 256, smem>>>(b_hh_f, b_hh_b, out, has_states);

    // output projection: [4096,2048] @ [2048,32000] -> logits
    gemm_tf32<<<(MBS / 128) * (VV / 128), 256>>>(comb, W_out, b_out, out, MBS, VV, 2 * HH);
}

// round 6
// speedup vs baseline: 2.2775x; 2.2775x over previous
#include <cuda_runtime.h>
#include <cuda_fp16.h>
#include <math.h>
#include <stdint.h>

// ---------------------------------------------------------------------------
// Problem constants
// ---------------------------------------------------------------------------
#define BB   32
#define SS   128
#define HH   1024
#define G4   4096
#define VV   32000
#define MBS  4096                      // B*S
#define LOGITS 131072000LL             // B*S*V

// ---------------------------------------------------------------------------
// Device scratch
// ---------------------------------------------------------------------------
__device__ __half    g_emb [MBS * HH];             // 8 MB   [m][H] fp16
__device__ float     g_xp  [2L * MBS * G4];        // 128 MB [dir][m][4H] fp32
__device__ __half    g_comb[MBS * 2 * HH];         // 16 MB  [m][2H] fp16
__device__ uint32_t  g_whhp[2L * 512 * G4];        // 16 MB  packed fp16 pairs
__device__ uint32_t  g_wihp[2L * 512 * G4];        // 16 MB  packed fp16 pairs
__device__ uint32_t  g_wtp [1024L * VV];           // 128 MB packed fp16 pairs
__device__ __half    g_h   [2 * 2 * BB * HH];      // [dir][pingpong][b][H]
__device__ unsigned  g_bar [SS];                   // barrier counters (BSS zero)

// ---------------------------------------------------------------------------
// Helpers
// ---------------------------------------------------------------------------
__device__ __forceinline__ float4 ldcg4(const float4* p) {
    float4 v;
    asm volatile("ld.global.cg.v4.f32 {%0,%1,%2,%3}, [%4];"
                 : "=f"(v.x), "=f"(v.y), "=f"(v.z), "=f"(v.w) : "l"(p));
    return v;
}
__device__ __forceinline__ uint32_t ldcg_u32(const uint32_t* p) {
    uint32_t v;
    asm volatile("ld.global.cg.u32 %0, [%1];" : "=r"(v) : "l"(p));
    return v;
}
__device__ __forceinline__ float sigm(float x) { return 1.f / (1.f + expf(-x)); }

__device__ __forceinline__ void mma_fp16(float* d, const uint32_t* a, const uint32_t* b) {
    asm volatile(
        "mma.sync.aligned.m16n8k16.row.col.f32.f16.f16.f32 "
        "{%0,%1,%2,%3},{%4,%5,%6,%7},{%8,%9},{%0,%1,%2,%3};"
        : "+f"(d[0]), "+f"(d[1]), "+f"(d[2]), "+f"(d[3])
        : "r"(a[0]), "r"(a[1]), "r"(a[2]), "r"(a[3]), "r"(b[0]), "r"(b[1]));
}

__device__ __forceinline__ void cpasync16(uint32_t dst, const void* src) {
    asm volatile("cp.async.cg.shared.global [%0], [%1], 16;" :: "r"(dst), "l"(src));
}
__device__ __forceinline__ uint32_t smem_u32(const void* p) {
    uint32_t a;
    asm("{ .reg .u64 t; cvta.to.shared.u64 t, %1; cvt.u32.u64 %0, t; }" : "=r"(a) : "l"(p));
    return a;
}

// ---------------------------------------------------------------------------
// Kernel: embedding gather -> fp16
// ---------------------------------------------------------------------------
__global__ void embed_kernel(const int* __restrict__ x, const float* __restrict__ embed) {
    int m = blockIdx.x;
    int idx = x[m];
    const float4* src = (const float4*)(embed + (size_t)idx * HH);
    __half2* dst = (__half2*)(g_emb + (size_t)m * HH);
    float4 v = src[threadIdx.x];
    dst[threadIdx.x * 2]     = __floats2half2_rn(v.x, v.y);
    dst[threadIdx.x * 2 + 1] = __floats2half2_rn(v.z, v.w);
}

// ---------------------------------------------------------------------------
// Kernel: pack fp32 weight [K][N] -> uint32 [K/2][N], word = (h[2kk], h[2kk+1])
// ---------------------------------------------------------------------------
__global__ void pack_w(const float* __restrict__ src, uint32_t* __restrict__ dst,
                       int K2, int N) {
    size_t n = (size_t)K2 * N;
    for (size_t i = (size_t)blockIdx.x * blockDim.x + threadIdx.x; i < n;
         i += (size_t)gridDim.x * blockDim.x) {
        size_t kk = i / N, col = i - kk * N;
        float lo = src[(2 * kk)     * (size_t)N + col];
        float hi = src[(2 * kk + 1) * (size_t)N + col];
        __half2 h = __floats2half2_rn(lo, hi);
        dst[i] = *(uint32_t*)&h;
    }
}

// ---------------------------------------------------------------------------
// Kernel: fp16 GEMM  C[M,N] = A[M,K] @ B[K,N] + bias[N]   (B passed packed)
// 128x128 CTA tile, K-chunk 32, 3-stage cp.async pipeline, 256 thr,
// 8 warps as 4(wm) x 2(wn), warp tile 32x64, mma m16n8k16 f32 accum.
// A: fp16 row-major [M][K]. Bp: uint32 [K/2][N] (fp16 k-pair packed).
// Requires M%128==0, N%128==0, K%32==0.
// ---------------------------------------------------------------------------
#define STAGES 3
#define APITCH 20                 // uint32 words per A row (16 data + 4 pad)
#define BPITCH 136                // uint32 words per B row (128 data + 8 pad)
#define ASTG   (128 * APITCH)     // 2560 words
#define BSTG   (16 * BPITCH)      // 2176 words
#define STGW   (ASTG + BSTG)      // 4736 words / stage
#define GSMEM  (STAGES * STGW * 4)

__global__ __launch_bounds__(256, 2) void gemm_fp16(
    const __half* __restrict__ A, const uint32_t* __restrict__ Bp,
    const float* __restrict__ bias, float* __restrict__ C,
    int M, int N, int K, int tiles_m)
{
    extern __shared__ __align__(16) uint32_t smw[];
    uint32_t sb = smem_u32(smw);

    int tid = threadIdx.x, lane = tid & 31, warp = tid >> 5;
    int gid = lane >> 2, tq = lane & 3;
    int wm = warp >> 1, wn = warp & 1;

    int mt = blockIdx.x % tiles_m, nt = blockIdx.x / tiles_m;
    size_t m0 = (size_t)mt * 128, n0 = (size_t)nt * 128;
    int CH = K >> 5;

    // per-thread cp.async assignment: 2 A-ops + 2 B-ops of 16B per chunk
    // A ops (512): id in [0,512): r=id>>2, seg=id&3
    // B ops (512): id in [0,512): kk=id>>5, seg=id&31
    const __half* asrc0 = A + (m0 + (tid >> 2)) * (size_t)K + (tid & 3) * 8;
    const __half* asrc1 = A + (m0 + ((tid + 256) >> 2)) * (size_t)K + (tid & 3) * 8;
    uint32_t adst0 = ((tid >> 2) * APITCH + (tid & 3) * 4) * 4;
    uint32_t adst1 = (((tid + 256) >> 2) * APITCH + (tid & 3) * 4) * 4;
    const uint32_t* bsrc0 = Bp + (size_t)(tid >> 5) * N + n0 + (tid & 31) * 4;
    const uint32_t* bsrc1 = Bp + (size_t)((tid + 256) >> 5) * N + n0 + (tid & 31) * 4;
    uint32_t bdst0 = (ASTG + (tid >> 5) * BPITCH + (tid & 31) * 4) * 4;
    uint32_t bdst1 = (ASTG + ((tid + 256) >> 5) * BPITCH + (tid & 31) * 4) * 4;

    float acc[2][8][4];
#pragma unroll
    for (int i = 0; i < 2; i++)
#pragma unroll
        for (int j = 0; j < 8; j++)
#pragma unroll
            for (int e = 0; e < 4; e++) acc[i][j][e] = 0.f;

#define ISSUE_CHUNK(c, s) {                                                  \
    uint32_t stb = sb + (uint32_t)(s) * (STGW * 4);                          \
    int k0h = (c) << 5;            /* halves */                              \
    size_t k0w = (size_t)((c) << 4) * N;  /* packed rows */                  \
    cpasync16(stb + adst0, asrc0 + k0h);                                     \
    cpasync16(stb + adst1, asrc1 + k0h);                                     \
    cpasync16(stb + bdst0, bsrc0 + k0w);                                     \
    cpasync16(stb + bdst1, bsrc1 + k0w);                                     \
}

    // prologue: first STAGES-1 chunks
    ISSUE_CHUNK(0, 0);
    asm volatile("cp.async.commit_group;");
    ISSUE_CHUNK(1, 1);
    asm volatile("cp.async.commit_group;");

    for (int c = 0; c < CH; c++) {
        asm volatile("cp.async.wait_group 1;");
        __syncthreads();
        if (c + 2 < CH) { int s = (c + 2) % STAGES; ISSUE_CHUNK(c + 2, s); }
        asm volatile("cp.async.commit_group;");

        const uint32_t* sA = smw + (c % STAGES) * STGW;
        const uint32_t* sB = sA + ASTG;
#pragma unroll
        for (int h = 0; h < 2; h++) {
            int kk = h * 8;
            uint32_t a[2][4], b[8][2];
#pragma unroll
            for (int mi = 0; mi < 2; mi++) {
                int r = wm * 32 + mi * 16 + gid;
                a[mi][0] = sA[r * APITCH + kk + tq];
                a[mi][1] = sA[(r + 8) * APITCH + kk + tq];
                a[mi][2] = sA[r * APITCH + kk + tq + 4];
                a[mi][3] = sA[(r + 8) * APITCH + kk + tq + 4];
            }
#pragma unroll
            for (int ni = 0; ni < 8; ni++) {
                int cc = wn * 64 + ni * 8 + gid;
                b[ni][0] = sB[(kk + tq) * BPITCH + cc];
                b[ni][1] = sB[(kk + tq + 4) * BPITCH + cc];
            }
#pragma unroll
            for (int mi = 0; mi < 2; mi++)
#pragma unroll
                for (int ni = 0; ni < 8; ni++)
                    mma_fp16(acc[mi][ni], a[mi], b[ni]);
        }
    }

    // epilogue: add bias, store fp32
#pragma unroll
    for (int mi = 0; mi < 2; mi++) {
#pragma unroll
        for (int ni = 0; ni < 8; ni++) {
            size_t r = m0 + wm * 32 + mi * 16 + gid;
            size_t c = n0 + wn * 64 + ni * 8 + 2 * tq;
            float2 bv = *(const float2*)(bias + c);
            float2 o0 = make_float2(acc[mi][ni][0] + bv.x, acc[mi][ni][1] + bv.y);
            float2 o1 = make_float2(acc[mi][ni][2] + bv.x, acc[mi][ni][3] + bv.y);
            *(float2*)(C + r * (size_t)N + c) = o0;
            *(float2*)(C + (r + 8) * (size_t)N + c) = o1;
        }
    }
}

// ---------------------------------------------------------------------------
// Grid barrier (self-resetting for graph replay)
// ---------------------------------------------------------------------------
__device__ __forceinline__ void gbar(int idx) {
    __threadfence();
    __syncthreads();
    if (threadIdx.x == 0) {
        unsigned a = atomicAdd(&g_bar[idx], 1u);
        if (a + 1u < 128u) {
            while (((volatile unsigned*)g_bar)[idx] < 128u) __nanosleep(64);
        }
        if (blockIdx.x == 0 && idx > 0) ((volatile unsigned*)g_bar)[idx - 1] = 0u;
    }
    __syncthreads();
}

// ---------------------------------------------------------------------------
// Kernel: persistent bidirectional LSTM recurrence (fp16 operands).
// 128 CTAs x 256 thr. CTAs [0,64) fwd, [64,128) bwd. CTA owns 16 hidden units
// -> 64 gate cols. Warp w: gate (w&3), K-half (w>>2); mma m16n8k16 fp16.
// W_hh packed uint32 [512][4096] from L2; h exchanged fp16 via ping-pong.
// ---------------------------------------------------------------------------
#define HPITCH 516   // uint32 words per h row (512 data + 4 pad)

__global__ __launch_bounds__(256, 1) void lstm_kernel(
    const float* __restrict__ bhh_f, const float* __restrict__ bhh_b,
    float* __restrict__ out, int has_states)
{
    extern __shared__ uint32_t smu[];
    uint32_t* h32   = smu;                          // [32][HPITCH]
    float* g_s      = (float*)(smu + 32 * HPITCH);  // [64][68]
    float* c_s      = g_s + 64 * 68;                // [512]
    float* bias_s   = c_s + 512;                    // [64]

    int dir = blockIdx.x >> 6;
    int cid = blockIdx.x & 63;
    int j0  = cid * 16;
    const uint32_t* Wp = g_whhp + (size_t)dir * 512 * G4;
    const float* bh = dir ? bhh_b : bhh_f;
    const float* xp = g_xp + (size_t)dir * MBS * G4;
    __half* hbuf = g_h + (size_t)dir * 2 * BB * HH;

    int tid = threadIdx.x;
    int lane = tid & 31, warp = tid >> 5;
    int gid = lane >> 2, tq = lane & 3;
    int gate = warp & 3, kh = warp >> 2;

    for (int i = tid; i < 512; i += 256) c_s[i] = 0.f;
    if (tid < 64) bias_s[tid] = bh[(tid >> 4) * HH + j0 + (tid & 15)];
    for (int i = cid * 256 + tid; i < BB * HH; i += 64 * 256) hbuf[i] = __float2half(0.f);
    gbar(0);

    int colb = gate * 1024 + j0 + gid;   // + ni*8

    for (int step = 0; step < SS; step++) {
        int tseq = dir ? (SS - 1 - step) : step;
        int cur = step & 1, nxt = cur ^ 1;
        const __half* hg = hbuf + cur * BB * HH;

        // copy h (fp16) -> SMEM, L1 bypass
        for (int idx = tid; idx < 4096; idx += 256) {
            int r = idx >> 7, seg = idx & 127;
            float4 v = ldcg4((const float4*)hg + r * 128 + seg);
            *(float4*)(h32 + r * HPITCH + seg * 4) = v;
        }
        __syncthreads();

        float acc[2][2][4];
#pragma unroll
        for (int i = 0; i < 2; i++)
#pragma unroll
            for (int j = 0; j < 2; j++)
#pragma unroll
                for (int e = 0; e < 4; e++) acc[i][j][e] = 0.f;

        int kend = kh * 256 + 256;
#pragma unroll 4
        for (int kb2 = kh * 256; kb2 < kend; kb2 += 8) {
            uint32_t a[2][4];
#pragma unroll
            for (int mi = 0; mi < 2; mi++) {
                int r = mi * 16 + gid;
                a[mi][0] = h32[r * HPITCH + kb2 + tq];
                a[mi][1] = h32[(r + 8) * HPITCH + kb2 + tq];
                a[mi][2] = h32[r * HPITCH + kb2 + tq + 4];
                a[mi][3] = h32[(r + 8) * HPITCH + kb2 + tq + 4];
            }
#pragma unroll
            for (int ni = 0; ni < 2; ni++) {
                uint32_t bf[2];
                bf[0] = ldcg_u32(Wp + (size_t)(kb2 + tq) * G4 + colb + ni * 8);
                bf[1] = ldcg_u32(Wp + (size_t)(kb2 + tq + 4) * G4 + colb + ni * 8);
                mma_fp16(acc[0][ni], a[0], bf);
                mma_fp16(acc[1][ni], a[1], bf);
            }
        }

        float* gp = g_s + (kh * 32) * 68 + gate * 16;
#pragma unroll
        for (int mi = 0; mi < 2; mi++)
#pragma unroll
            for (int ni = 0; ni < 2; ni++) {
                int r = mi * 16 + gid, c = ni * 8 + 2 * tq;
                gp[r * 68 + c]           = acc[mi][ni][0];
                gp[r * 68 + c + 1]       = acc[mi][ni][1];
                gp[(r + 8) * 68 + c]     = acc[mi][ni][2];
                gp[(r + 8) * 68 + c + 1] = acc[mi][ni][3];
            }
        __syncthreads();

        __half* hn = hbuf + nxt * BB * HH;
        for (int it = tid; it < 512; it += 256) {
            int b = it >> 4, jj = it & 15;
            const float* xr = xp + ((size_t)(b * SS + tseq)) * G4 + j0 + jj;
            float gq[4];
#pragma unroll
            for (int q = 0; q < 4; q++)
                gq[q] = g_s[b * 68 + q * 16 + jj] + g_s[(32 + b) * 68 + q * 16 + jj]
                      + xr[(size_t)q * 1024] + bias_s[q * 16 + jj];
            float iv = sigm(gq[0]);
            float fv = sigm(gq[1]);
            float gv = tanhf(gq[2]);
            float ov = sigm(gq[3]);
            float c = fv * c_s[it] + iv * gv;
            float h = ov * tanhf(c);
            c_s[it] = c;
            hn[b * HH + j0 + jj] = __float2half(h);
            g_comb[((size_t)(b * SS + tseq)) * 2 * HH + dir * HH + j0 + jj] = __float2half(h);
            if (has_states && step == SS - 1) {
                size_t base = LOGITS + (size_t)dir * 2 * BB * HH;
                out[base + b * HH + j0 + jj] = h;            // hT
                out[base + BB * HH + b * HH + j0 + jj] = c;  // cT
            }
        }
        if (step < SS - 1) gbar(step + 1);
        else __syncthreads();
    }
    if (blockIdx.x == 0 && threadIdx.x == 0)
        ((volatile unsigned*)g_bar)[SS - 1] = 0u;
}

// ---------------------------------------------------------------------------
// Launch
// ---------------------------------------------------------------------------
extern "C" void kernel_launch(void* const* d_in, const int* in_sizes, int n_in,
                              void* d_out, int out_size) {
    const int*   x      = (const int*)d_in[0];
    const float* embed  = (const float*)d_in[1];
    const float* W_ih_f = (const float*)d_in[2];
    const float* b_ih_f = (const float*)d_in[3];
    const float* W_hh_f = (const float*)d_in[4];
    const float* b_hh_f = (const float*)d_in[5];
    const float* W_ih_b = (const float*)d_in[6];
    const float* b_ih_b = (const float*)d_in[7];
    const float* W_hh_b = (const float*)d_in[8];
    const float* b_hh_b = (const float*)d_in[9];
    const float* W_out  = (const float*)d_in[10];
    const float* b_out  = (const float*)d_in[11];
    float* out = (float*)d_out;

    void *pe, *pxp, *pcomb, *pwih, *pwhh, *pwt;
    cudaGetSymbolAddress(&pe, g_emb);
    cudaGetSymbolAddress(&pxp, g_xp);
    cudaGetSymbolAddress(&pcomb, g_comb);
    cudaGetSymbolAddress(&pwih, g_wihp);
    cudaGetSymbolAddress(&pwhh, g_whhp);
    cudaGetSymbolAddress(&pwt, g_wtp);
    __half*   emb  = (__half*)pe;
    float*    xp   = (float*)pxp;
    __half*   comb = (__half*)pcomb;
    uint32_t* wih  = (uint32_t*)pwih;
    uint32_t* whh  = (uint32_t*)pwhh;
    uint32_t* wt   = (uint32_t*)pwt;

    embed_kernel<<<MBS, 256>>>(x, embed);
    pack_w<<<1024, 256>>>(W_ih_f, wih, 512, G4);
    pack_w<<<1024, 256>>>(W_ih_b, wih + (size_t)512 * G4, 512, G4);
    pack_w<<<1024, 256>>>(W_hh_f, whh, 512, G4);
    pack_w<<<1024, 256>>>(W_hh_b, whh + (size_t)512 * G4, 512, G4);
    pack_w<<<2048, 256>>>(W_out, wt, 1024, VV);

    cudaFuncSetAttribute(gemm_fp16, cudaFuncAttributeMaxDynamicSharedMemorySize, GSMEM);

    // input projections: [4096,1024] @ [1024,4096]  (tiles 32 x 32)
    gemm_fp16<<<32 * 32, 256, GSMEM>>>(emb, wih, b_ih_f, xp, MBS, G4, HH, 32);
    gemm_fp16<<<32 * 32, 256, GSMEM>>>(emb, wih + (size_t)512 * G4, b_ih_b,
                                       xp + (size_t)MBS * G4, MBS, G4, HH, 32);

    int smem = (32 * HPITCH + 64 * 68 + 512 + 64) * 4;
    cudaFuncSetAttribute(lstm_kernel, cudaFuncAttributeMaxDynamicSharedMemorySize, smem);
    long long need = LOGITS + 4LL * BB * HH;
    int has_states = ((long long)out_size >= need) ? 1 : 0;
    lstm_kernel<<<128, 256, smem>>>(b_hh_f, b_hh_b, out, has_states);

    // output projection: [4096,2048] @ [2048,32000]  (tiles 32 x 250)
    gemm_fp16<<<32 * 250, 256, GSMEM>>>(comb, wt, b_out, out, MBS, VV, 2 * HH, 32);
}